// round 1
// baseline (speedup 1.0000x reference)
#include <cuda_runtime.h>
#include <math.h>

#define NCAM 6
#define NH   8
#define NP   4
#define DD   256
#define HH   20
#define WW   40
#define HWW  800
#define LQ   4800
#define HDIM 32
#define NOFF 384
#define TWO_PI 6.283185307179586f

// ------------------------- scratch (static device arrays) -------------------
__device__ float g_res  [LQ*DD];    // residual / x_nhwc
__device__ float g_srcb [LQ*DD];    // src (conv0 output)
__device__ float g_qry  [LQ*DD];    // query = spc
__device__ float g_keyb [LQ*DD];
__device__ float g_valb [LQ*DD];
__device__ float g_offb [LQ*NOFF];
__device__ float g_posb [HWW*DD];
__device__ float g_meanb[NCAM*DD];
__device__ float g_gtokb[NCAM*DD];
__device__ float g_attb [LQ*DD];
__device__ float g_t1b  [LQ*DD];
__device__ float g_t2b  [LQ*DD];
__device__ float g_lnb  [LQ*DD];

// ------------------------- kernels -----------------------------------------

// x (6,256,800) -> res (4800,256)  [per-cam 256x800 transpose]
__global__ void transpose_in_kernel(const float* __restrict__ x, float* __restrict__ res)
{
    __shared__ float tile[32][33];
    int cam = blockIdx.z;
    int c0  = blockIdx.y * 32;
    int p0  = blockIdx.x * 32;
    int tx = threadIdx.x, ty = threadIdx.y;
    #pragma unroll
    for (int i = ty; i < 32; i += 8)
        tile[i][tx] = x[(size_t)(cam*DD + c0 + i)*HWW + p0 + tx];
    __syncthreads();
    #pragma unroll
    for (int i = ty; i < 32; i += 8)
        res[(size_t)(cam*HWW + p0 + i)*DD + c0 + tx] = tile[tx][i];
}

// sine positional encoding into (800,256)
__global__ void pos_kernel(float* __restrict__ pos)
{
    int pix = blockIdx.x;
    int c   = threadIdx.x;
    int i = pix / WW, j = pix % WW;
    float v; int cc;
    if (c < 128) { v = (float)(i + 1) / (20.0f + 1e-6f) * TWO_PI; cc = c; }
    else         { v = (float)(j + 1) / (40.0f + 1e-6f) * TWO_PI; cc = c - 128; }
    float expo = (2.0f * (float)(cc / 2)) / 128.0f;
    float dt = powf(10000.0f, expo);
    float ph = v / dt;
    pos[(size_t)pix*DD + c] = (cc & 1) ? cosf(ph) : sinf(ph);
}

// query = src + pos + cam_emb
__global__ void add_pos_cam_kernel(const float* __restrict__ src, const float* __restrict__ pos,
                                   const float* __restrict__ cam_emb, float* __restrict__ qry)
{
    int q = blockIdx.x, c = threadIdx.x;
    int cam = q / HWW, pix = q % HWW;
    qry[(size_t)q*DD + c] = src[(size_t)q*DD + c] + pos[(size_t)pix*DD + c] + cam_emb[cam*DD + c];
}

// mean over HW per camera
__global__ void mean_kernel(const float* __restrict__ qry, float* __restrict__ meanb)
{
    int cam = blockIdx.x, c = threadIdx.x;
    float s = 0.f;
    for (int p = 0; p < HWW; ++p)
        s += qry[(size_t)(cam*HWW + p)*DD + c];
    meanb[cam*DD + c] = s * (1.0f/(float)HWW);
}

// g = mean @ conv2_w^T + conv2_b  (6x256x256, tiny)
__global__ void gtok_kernel(const float* __restrict__ meanb, const float* __restrict__ w,
                            const float* __restrict__ b, float* __restrict__ gtok)
{
    int cam = blockIdx.x, o = threadIdx.x;
    float s = b[o];
    const float* mrow = meanb + cam*DD;
    const float* wrow = w + (size_t)o*DD;
    for (int c = 0; c < DD; ++c) s += mrow[c] * wrow[c];
    gtok[cam*DD + o] = s;
}

// C[M,N] = A[M,K] * B[N,K]^T + bias[N]  (optionally relu). 64x64 tiles, BK=16.
__global__ __launch_bounds__(256)
void gemm_bias_kernel(const float* __restrict__ A, const float* __restrict__ B,
                      const float* __restrict__ bias, float* __restrict__ C,
                      int M, int N, int K, int relu)
{
    __shared__ float As[16][68];
    __shared__ float Bs[16][68];
    int tid = threadIdx.x;
    int bm = blockIdx.y * 64, bn = blockIdx.x * 64;
    int tr = tid >> 4, tc = tid & 15;
    int lr = tid >> 2;
    int lk = (tid & 3) << 2;
    float acc[4][4];
    #pragma unroll
    for (int i = 0; i < 4; ++i)
        #pragma unroll
        for (int j = 0; j < 4; ++j) acc[i][j] = 0.f;

    for (int k0 = 0; k0 < K; k0 += 16) {
        float4 a = *(const float4*)(A + (size_t)(bm + lr)*K + k0 + lk);
        float4 b = *(const float4*)(B + (size_t)(bn + lr)*K + k0 + lk);
        As[lk+0][lr] = a.x; As[lk+1][lr] = a.y; As[lk+2][lr] = a.z; As[lk+3][lr] = a.w;
        Bs[lk+0][lr] = b.x; Bs[lk+1][lr] = b.y; Bs[lk+2][lr] = b.z; Bs[lk+3][lr] = b.w;
        __syncthreads();
        #pragma unroll
        for (int kk = 0; kk < 16; ++kk) {
            float ar[4], br[4];
            #pragma unroll
            for (int i = 0; i < 4; ++i) { ar[i] = As[kk][tr*4+i]; br[i] = Bs[kk][tc*4+i]; }
            #pragma unroll
            for (int i = 0; i < 4; ++i)
                #pragma unroll
                for (int j = 0; j < 4; ++j) acc[i][j] += ar[i]*br[j];
        }
        __syncthreads();
    }
    #pragma unroll
    for (int i = 0; i < 4; ++i) {
        int m = bm + tr*4 + i;
        #pragma unroll
        for (int j = 0; j < 4; ++j) {
            int n = bn + tc*4 + j;
            float v = acc[i][j] + bias[n];
            if (relu) v = fmaxf(v, 0.f);
            C[(size_t)m*N + n] = v;
        }
    }
}

// fused deformable gather + attention. 1 warp per (q, head); lane = channel.
__global__ __launch_bounds__(256)
void attn_kernel(const float* __restrict__ qry, const float* __restrict__ keys,
                 const float* __restrict__ vals, const float* __restrict__ offs,
                 const float* __restrict__ gtok, float* __restrict__ attn_out)
{
    int q    = blockIdx.x;
    int h    = threadIdx.y;
    int lane = threadIdx.x;
    int pix = q % HWW;
    int row = pix / WW, col = pix % WW;
    float qd = qry[(size_t)q*DD + h*HDIM + lane] * 0.17677669529663687f; // 1/sqrt(32)

    float logit[30], vv[30];
    const float* offq = offs + (size_t)q*NOFF + h*(NCAM*NP*2);

    #pragma unroll
    for (int l = 0; l < NCAM; ++l) {
        const float* kb = keys + (size_t)(l*HWW)*DD + h*HDIM + lane;
        const float* vb = vals + (size_t)(l*HWW)*DD + h*HDIM + lane;
        #pragma unroll
        for (int p = 0; p < NP; ++p) {
            float ox = offq[l*NP*2 + p*2 + 0];
            float oy = offq[l*NP*2 + p*2 + 1];
            // loc_x*W - 0.5 = col + ox ; loc_y*H - 0.5 = row + oy (exact)
            float px = (float)col + ox;
            float py = (float)row + oy;
            float x0f = floorf(px), y0f = floorf(py);
            float fx = px - x0f, fy = py - y0f;
            int x0 = (int)x0f, y0 = (int)y0f;
            float ka = 0.f, va = 0.f;
            #pragma unroll
            for (int dy = 0; dy < 2; ++dy) {
                #pragma unroll
                for (int dx = 0; dx < 2; ++dx) {
                    int xi = x0 + dx, yi = y0 + dy;
                    if (xi >= 0 && xi < WW && yi >= 0 && yi < HH) {
                        float w = (dx ? fx : 1.f - fx) * (dy ? fy : 1.f - fy);
                        int idx = (yi*WW + xi)*DD;
                        ka += w * kb[idx];
                        va += w * vb[idx];
                    }
                }
            }
            float d = qd * ka;
            #pragma unroll
            for (int o = 16; o; o >>= 1) d += __shfl_xor_sync(0xffffffffu, d, o);
            logit[l*5 + p] = d;
            vv[l*5 + p] = va;
        }
        // global token (5th point): k == v == g[l, h*32+lane]
        float kg = gtok[l*DD + h*HDIM + lane];
        float d = qd * kg;
        #pragma unroll
        for (int o = 16; o; o >>= 1) d += __shfl_xor_sync(0xffffffffu, d, o);
        logit[l*5 + 4] = d;
        vv[l*5 + 4] = kg;
    }
    float m = -1e30f;
    #pragma unroll
    for (int i = 0; i < 30; ++i) m = fmaxf(m, logit[i]);
    float s = 0.f, o = 0.f;
    #pragma unroll
    for (int i = 0; i < 30; ++i) { float e = expf(logit[i] - m); s += e; o += e * vv[i]; }
    attn_out[(size_t)q*DD + h*HDIM + lane] = o / s;
}

// block-wide sum over 256 threads
__device__ __forceinline__ float block_sum_256(float v, float* sh)
{
    int lane = threadIdx.x & 31, wid = threadIdx.x >> 5;
    #pragma unroll
    for (int o = 16; o; o >>= 1) v += __shfl_xor_sync(0xffffffffu, v, o);
    if (lane == 0) sh[wid] = v;
    __syncthreads();
    float t = 0.f;
    #pragma unroll
    for (int i = 0; i < 8; ++i) t += sh[i];
    __syncthreads();
    return t;
}

// out = LN(A + Bd) * gamma + beta   (row-major out)
__global__ __launch_bounds__(256)
void ln_kernel(const float* __restrict__ A, const float* __restrict__ Bd,
               const float* __restrict__ gam, const float* __restrict__ bet,
               float* __restrict__ out)
{
    __shared__ float sh[8];
    int q = blockIdx.x, c = threadIdx.x;
    float v = A[(size_t)q*DD + c] + Bd[(size_t)q*DD + c];
    float mu = block_sum_256(v, sh) * (1.f/(float)DD);
    float d = v - mu;
    float var = block_sum_256(d*d, sh) * (1.f/(float)DD);
    out[(size_t)q*DD + c] = d * rsqrtf(var + 1e-5f) * gam[c] + bet[c];
}

// final LN + transpose to (6,256,20,40)
__global__ __launch_bounds__(256)
void ln_out_kernel(const float* __restrict__ A, const float* __restrict__ Bd,
                   const float* __restrict__ gam, const float* __restrict__ bet,
                   float* __restrict__ out)
{
    __shared__ float sh[8];
    int q = blockIdx.x, c = threadIdx.x;
    float v = A[(size_t)q*DD + c] + Bd[(size_t)q*DD + c];
    float mu = block_sum_256(v, sh) * (1.f/(float)DD);
    float d = v - mu;
    float var = block_sum_256(d*d, sh) * (1.f/(float)DD);
    float r = d * rsqrtf(var + 1e-5f) * gam[c] + bet[c];
    int cam = q / HWW, pix = q % HWW;
    out[(size_t)(cam*DD + c)*HWW + pix] = r;
}

// ------------------------- launch ------------------------------------------
extern "C" void kernel_launch(void* const* d_in, const int* in_sizes, int n_in,
                              void* d_out, int out_size)
{
    const float* x       = (const float*)d_in[0];
    const float* conv0_w = (const float*)d_in[1];
    const float* conv0_b = (const float*)d_in[2];
    const float* conv2_w = (const float*)d_in[3];
    const float* conv2_b = (const float*)d_in[4];
    const float* cam_emb = (const float*)d_in[5];
    const float* off_w   = (const float*)d_in[6];
    const float* off_b   = (const float*)d_in[7];
    const float* val_w   = (const float*)d_in[8];
    const float* val_b   = (const float*)d_in[9];
    const float* key_w   = (const float*)d_in[10];
    const float* key_b   = (const float*)d_in[11];
    const float* out_w   = (const float*)d_in[12];
    const float* out_b   = (const float*)d_in[13];
    const float* conv1_w = (const float*)d_in[14];
    const float* conv1_b = (const float*)d_in[15];
    const float* norm0_g = (const float*)d_in[16];
    const float* norm0_b = (const float*)d_in[17];
    const float* lin1_w  = (const float*)d_in[18];
    const float* lin1_b  = (const float*)d_in[19];
    const float* lin2_w  = (const float*)d_in[20];
    const float* lin2_b  = (const float*)d_in[21];
    const float* norm2_g = (const float*)d_in[22];
    const float* norm2_b = (const float*)d_in[23];

    float *res, *srcb, *qry, *keyb, *valb, *offb, *posb, *meanb, *gtokb, *attb, *t1, *t2, *lnb;
    cudaGetSymbolAddress((void**)&res,   g_res);
    cudaGetSymbolAddress((void**)&srcb,  g_srcb);
    cudaGetSymbolAddress((void**)&qry,   g_qry);
    cudaGetSymbolAddress((void**)&keyb,  g_keyb);
    cudaGetSymbolAddress((void**)&valb,  g_valb);
    cudaGetSymbolAddress((void**)&offb,  g_offb);
    cudaGetSymbolAddress((void**)&posb,  g_posb);
    cudaGetSymbolAddress((void**)&meanb, g_meanb);
    cudaGetSymbolAddress((void**)&gtokb, g_gtokb);
    cudaGetSymbolAddress((void**)&attb,  g_attb);
    cudaGetSymbolAddress((void**)&t1,    g_t1b);
    cudaGetSymbolAddress((void**)&t2,    g_t2b);
    cudaGetSymbolAddress((void**)&lnb,   g_lnb);

    dim3 tb(32, 8);

    transpose_in_kernel<<<dim3(25, 8, NCAM), tb>>>(x, res);
    pos_kernel<<<HWW, DD>>>(posb);

    // src = residual @ conv0_w^T + conv0_b
    gemm_bias_kernel<<<dim3(DD/64, LQ/64), 256>>>(res, conv0_w, conv0_b, srcb, LQ, DD, DD, 0);
    add_pos_cam_kernel<<<LQ, DD>>>(srcb, posb, cam_emb, qry);

    // g token path (mean commutes through the linear layer)
    mean_kernel<<<NCAM, DD>>>(qry, meanb);
    gtok_kernel<<<NCAM, DD>>>(meanb, conv2_w, conv2_b, gtokb);

    // keys / values / offsets
    gemm_bias_kernel<<<dim3(DD/64, LQ/64), 256>>>(srcb, key_w, key_b, keyb, LQ, DD, DD, 0);
    gemm_bias_kernel<<<dim3(DD/64, LQ/64), 256>>>(srcb, val_w, val_b, valb, LQ, DD, DD, 0);
    gemm_bias_kernel<<<dim3(NOFF/64, LQ/64), 256>>>(qry, off_w, off_b, offb, LQ, NOFF, DD, 0);

    // fused gather + attention
    attn_kernel<<<LQ, tb>>>(qry, keyb, valb, offb, gtokb, attb);

    // output projections
    gemm_bias_kernel<<<dim3(DD/64, LQ/64), 256>>>(attb, out_w, out_b, t1, LQ, DD, DD, 0);
    gemm_bias_kernel<<<dim3(DD/64, LQ/64), 256>>>(t1, conv1_w, conv1_b, t2, LQ, DD, DD, 0);

    // LN0(residual + out)
    ln_kernel<<<LQ, DD>>>(res, t2, norm0_g, norm0_b, lnb);

    // FFN
    gemm_bias_kernel<<<dim3(DD/64, LQ/64), 256>>>(lnb, lin1_w, lin1_b, t1, LQ, DD, DD, 1);
    gemm_bias_kernel<<<dim3(DD/64, LQ/64), 256>>>(t1, lin2_w, lin2_b, t2, LQ, DD, DD, 0);

    // LN2 + transpose to output layout
    ln_out_kernel<<<LQ, DD>>>(lnb, t2, norm2_g, norm2_b, (float*)d_out);
}